// round 1
// baseline (speedup 1.0000x reference)
#include <cuda_runtime.h>
#include <math.h>

#define BB   64
#define LL   2048
#define VV   30
#define EE   128
#define GG   8
#define GEGE 1024
#define CC   64
#define FF   128
#define OO   30
#define NDND 9

// ---------------- scratch (device globals; no runtime allocation) ----------
__device__ float g_res[2][(size_t)BB * LL * CC];   // ping-pong residual [b][t][c]
__device__ float g_skips[(size_t)BB * LL * CC];    // skip accumulator   [b][t][c]
__device__ float g_embg[BB * GEGE];                // flattened global embedding
__device__ float g_HF[NDND * BB * CC];             // per-layer conditioning (f)
__device__ float g_HG[NDND * BB * CC];             // per-layer conditioning (g)
__device__ float g_M0[VV * CC];                    // folded initial conv, tap 0
__device__ float g_M1[VV * CC];                    // folded initial conv, tap 1

// ---------------- K0: fold embedding+initial conv into lookup tables -------
__global__ void __launch_bounds__(64) k_precompute_M(
    const float* __restrict__ emb, const float* __restrict__ wc)
{
    int v = blockIdx.x, c = threadIdx.x;
    float a0 = 0.f, a1 = 0.f;
    if (v != 0) {  // padding_idx=0 -> embedding row 0 is zero
        for (int e = 0; e < EE; e++) {
            float x = emb[v * EE + e];
            a0 = fmaf(x, wc[(c * EE + e) * 2 + 0], a0);
            a1 = fmaf(x, wc[(c * EE + e) * 2 + 1], a1);
        }
    }
    g_M0[v * CC + c] = a0;
    g_M1[v * CC + c] = a1;
}

// ---------------- K1: global embedding ------------------------------------
__global__ void __launch_bounds__(256) k_embg(
    const int* __restrict__ gin, const float* __restrict__ emb)
{
    int b = blockIdx.x;
    for (int j = threadIdx.x; j < GEGE; j += 256) {
        int g = j >> 7, e = j & 127;
        int tok = gin[b * GG + g];
        g_embg[b * GEGE + j] = (tok == 0) ? 0.f : emb[tok * EE + e];
    }
}

// ---------------- K2: global conditioning vectors h_f/h_g per layer --------
__global__ void __launch_bounds__(128) k_H(
    const float* __restrict__ wlf, const float* __restrict__ blf,
    const float* __restrict__ wlg, const float* __restrict__ blg)
{
    __shared__ float se[GEGE];
    int i = blockIdx.x, b = blockIdx.y, tid = threadIdx.x;
    for (int j = tid; j < GEGE; j += 128) se[j] = g_embg[b * GEGE + j];
    __syncthreads();
    int c = tid & 63;
    bool isf = tid < 64;
    const float* w = (isf ? wlf : wlg) + ((size_t)i * CC + c) * GEGE;
    float acc = (isf ? blf : blg)[i * CC + c];
    for (int j = 0; j < GEGE; j += 4) {
        float4 wv = *(const float4*)(w + j);
        acc = fmaf(se[j], wv.x, acc);
        acc = fmaf(se[j + 1], wv.y, acc);
        acc = fmaf(se[j + 2], wv.z, acc);
        acc = fmaf(se[j + 3], wv.w, acc);
    }
    (isf ? g_HF : g_HG)[((size_t)i * BB + b) * CC + c] = acc;
}

// ---------------- K3: initial residual via lookup; zero skips --------------
__global__ void __launch_bounds__(256) k_init(
    const int* __restrict__ tok, const float* __restrict__ b_causal)
{
    __shared__ float sM0[VV * CC], sM1[VV * CC], sb[CC];
    int tid = threadIdx.x;
    for (int i = tid; i < VV * CC; i += 256) { sM0[i] = g_M0[i]; sM1[i] = g_M1[i]; }
    if (tid < CC) sb[tid] = b_causal[tid];
    __syncthreads();
    int b = blockIdx.y, tt0 = blockIdx.x * 64;
    const int* tb = tok + b * LL;
    float* ro = g_res[0] + (size_t)b * LL * CC;
    float* sk = g_skips + (size_t)b * LL * CC;
    for (int idx = tid; idx < 64 * 64; idx += 256) {
        int t = tt0 + (idx >> 6);
        int c = idx & 63;
        float r = sM1[tb[t] * CC + c] + sb[c];
        if (t > 0) r += sM0[tb[t - 1] * CC + c];
        size_t off = (size_t)t * CC + c;
        ro[off] = r;
        sk[off] = 0.f;
    }
}

// ---------------- K4: one dilated residual layer (fused) -------------------
// Per block: 64 timesteps x 64 channels of one batch.
// Phase 1: x_f/x_g = W*[res[t-d];res[t]] + bias + cond -> z = tanh*sigmoid
// Phase 2: skip = W_res*z ; res' = res + skip ; skips += skip
__global__ void __launch_bounds__(256) k_layer(
    const float* __restrict__ w_f, const float* __restrict__ b_f,
    const float* __restrict__ w_g, const float* __restrict__ b_g,
    const float* __restrict__ w_res, const float* __restrict__ b_res,
    int layer, int d)
{
    extern __shared__ float sm[];
    float* sWf0 = sm;                 // [k][c] 64x64
    float* sWf1 = sWf0 + 4096;
    float* sWg0 = sWf1 + 4096;
    float* sWg1 = sWg0 + 4096;
    float* sWr  = sWg1 + 4096;
    float* sCur = sWr + 4096;         // [c][t] stride 68
    float* sPrev = sCur + 64 * 68;
    float* sZ    = sPrev + 64 * 68;

    int tid = threadIdx.x;
    int b = blockIdx.y;
    int tt0 = blockIdx.x * 64;

    const float* wf = w_f + (size_t)layer * CC * CC * 2;
    const float* wg = w_g + (size_t)layer * CC * CC * 2;
    const float* wr = w_res + (size_t)layer * CC * CC;
    for (int idx = tid; idx < CC * CC; idx += 256) {
        int co = idx >> 6, ci = idx & 63;
        int tr = ci * 64 + co;
        sWf0[tr] = wf[idx * 2];
        sWf1[tr] = wf[idx * 2 + 1];
        sWg0[tr] = wg[idx * 2];
        sWg1[tr] = wg[idx * 2 + 1];
        sWr[tr]  = wr[idx];
    }

    const float* resin = g_res[layer & 1] + (size_t)b * LL * CC;
    for (int f = tid; f < 1024; f += 256) {
        int t = f >> 4;
        int c4 = (f & 15) * 4;
        float4 v = *(const float4*)(resin + (size_t)(tt0 + t) * CC + c4);
        sCur[(c4 + 0) * 68 + t] = v.x; sCur[(c4 + 1) * 68 + t] = v.y;
        sCur[(c4 + 2) * 68 + t] = v.z; sCur[(c4 + 3) * 68 + t] = v.w;
        int tp = tt0 + t - d;
        float4 p = make_float4(0.f, 0.f, 0.f, 0.f);
        if (tp >= 0) p = *(const float4*)(resin + (size_t)tp * CC + c4);
        sPrev[(c4 + 0) * 68 + t] = p.x; sPrev[(c4 + 1) * 68 + t] = p.y;
        sPrev[(c4 + 2) * 68 + t] = p.z; sPrev[(c4 + 3) * 68 + t] = p.w;
    }
    __syncthreads();

    int c0 = (tid & 15) * 4;
    int t0 = (tid >> 4) * 4;

    float af[4][4], ag[4][4];
    #pragma unroll
    for (int ci = 0; ci < 4; ci++) {
        float hf = b_f[layer * CC + c0 + ci] + g_HF[((size_t)layer * BB + b) * CC + c0 + ci];
        float hg = b_g[layer * CC + c0 + ci] + g_HG[((size_t)layer * BB + b) * CC + c0 + ci];
        #pragma unroll
        for (int tj = 0; tj < 4; tj++) { af[ci][tj] = hf; ag[ci][tj] = hg; }
    }

    #pragma unroll 4
    for (int k = 0; k < 64; k++) {
        float4 wf0 = *(const float4*)(sWf0 + k * 64 + c0);
        float4 wf1 = *(const float4*)(sWf1 + k * 64 + c0);
        float4 wg0 = *(const float4*)(sWg0 + k * 64 + c0);
        float4 wg1 = *(const float4*)(sWg1 + k * 64 + c0);
        float4 pv4 = *(const float4*)(sPrev + k * 68 + t0);
        float4 cv4 = *(const float4*)(sCur + k * 68 + t0);
        float w0a[4] = {wf0.x, wf0.y, wf0.z, wf0.w};
        float w1a[4] = {wf1.x, wf1.y, wf1.z, wf1.w};
        float g0a[4] = {wg0.x, wg0.y, wg0.z, wg0.w};
        float g1a[4] = {wg1.x, wg1.y, wg1.z, wg1.w};
        float pv[4] = {pv4.x, pv4.y, pv4.z, pv4.w};
        float cv[4] = {cv4.x, cv4.y, cv4.z, cv4.w};
        #pragma unroll
        for (int ci = 0; ci < 4; ci++)
            #pragma unroll
            for (int tj = 0; tj < 4; tj++) {
                af[ci][tj] = fmaf(w0a[ci], pv[tj], af[ci][tj]);
                af[ci][tj] = fmaf(w1a[ci], cv[tj], af[ci][tj]);
                ag[ci][tj] = fmaf(g0a[ci], pv[tj], ag[ci][tj]);
                ag[ci][tj] = fmaf(g1a[ci], cv[tj], ag[ci][tj]);
            }
    }

    #pragma unroll
    for (int ci = 0; ci < 4; ci++) {
        float z4[4];
        #pragma unroll
        for (int tj = 0; tj < 4; tj++) {
            float tf = tanhf(af[ci][tj]);
            float sg = 1.f / (1.f + expf(-ag[ci][tj]));
            z4[tj] = tf * sg;
        }
        *(float4*)(sZ + (c0 + ci) * 68 + t0) = make_float4(z4[0], z4[1], z4[2], z4[3]);
    }
    __syncthreads();

    float as[4][4];  // [tj][ci]
    #pragma unroll
    for (int tj = 0; tj < 4; tj++)
        #pragma unroll
        for (int ci = 0; ci < 4; ci++)
            as[tj][ci] = b_res[layer * CC + c0 + ci];

    #pragma unroll 4
    for (int k = 0; k < 64; k++) {
        float4 wrr = *(const float4*)(sWr + k * 64 + c0);
        float4 zz = *(const float4*)(sZ + k * 68 + t0);
        float wa[4] = {wrr.x, wrr.y, wrr.z, wrr.w};
        float za[4] = {zz.x, zz.y, zz.z, zz.w};
        #pragma unroll
        for (int tj = 0; tj < 4; tj++)
            #pragma unroll
            for (int ci = 0; ci < 4; ci++)
                as[tj][ci] = fmaf(wa[ci], za[tj], as[tj][ci]);
    }

    float* resout = g_res[(layer + 1) & 1] + (size_t)b * LL * CC;
    float* skp = g_skips + (size_t)b * LL * CC;
    #pragma unroll
    for (int tj = 0; tj < 4; tj++) {
        int t = tt0 + t0 + tj;
        size_t off = (size_t)t * CC + c0;
        float cx = sCur[(c0 + 0) * 68 + t0 + tj];
        float cy = sCur[(c0 + 1) * 68 + t0 + tj];
        float cz = sCur[(c0 + 2) * 68 + t0 + tj];
        float cw = sCur[(c0 + 3) * 68 + t0 + tj];
        float4 rn = make_float4(cx + as[tj][0], cy + as[tj][1],
                                cz + as[tj][2], cw + as[tj][3]);
        *(float4*)(resout + off) = rn;
        float4 so = *(const float4*)(skp + off);
        so.x += as[tj][0]; so.y += as[tj][1];
        so.z += as[tj][2]; so.w += as[tj][3];
        *(float4*)(skp + off) = so;
    }
}

// ---------------- K5: fused head: relu -> 64x128 -> relu -> 128x30 ---------
__global__ void __launch_bounds__(256) k_final(
    const float* __restrict__ w1, const float* __restrict__ b1,
    const float* __restrict__ w2, const float* __restrict__ b2,
    float* __restrict__ out)
{
    extern __shared__ float sm[];
    float* sS  = sm;                  // [c][t] 64x68, relu'd skips
    float* sW1 = sS + 64 * 68;        // [c][f] 64x128
    float* sH  = sW1 + 64 * 128;      // [f][t] 128x68
    float* sW2 = sH + 128 * 68;       // [f][o] 128x32 (padded)

    int tid = threadIdx.x;
    int b = blockIdx.y;
    int tt0 = blockIdx.x * 64;

    for (int idx = tid; idx < FF * CC; idx += 256) {
        int f = idx >> 6, c = idx & 63;
        sW1[c * 128 + f] = w1[idx];
    }
    for (int idx = tid; idx < 128 * 32; idx += 256) {
        int f = idx >> 5, o = idx & 31;
        sW2[idx] = (o < OO) ? w2[o * 128 + f] : 0.f;
    }
    const float* skp = g_skips + (size_t)b * LL * CC;
    for (int f4 = tid; f4 < 1024; f4 += 256) {
        int t = f4 >> 4, c4 = (f4 & 15) * 4;
        float4 v = *(const float4*)(skp + (size_t)(tt0 + t) * CC + c4);
        sS[(c4 + 0) * 68 + t] = fmaxf(v.x, 0.f);
        sS[(c4 + 1) * 68 + t] = fmaxf(v.y, 0.f);
        sS[(c4 + 2) * 68 + t] = fmaxf(v.z, 0.f);
        sS[(c4 + 3) * 68 + t] = fmaxf(v.w, 0.f);
    }
    __syncthreads();

    // Phase A: H[128][64] = relu(W1 * S + b1)
    {
        int f0 = (tid & 31) * 4;
        int t0 = (tid >> 5) * 8;
        float acc[4][8];
        #pragma unroll
        for (int fi = 0; fi < 4; fi++) {
            float bb = b1[f0 + fi];
            #pragma unroll
            for (int tj = 0; tj < 8; tj++) acc[fi][tj] = bb;
        }
        #pragma unroll 4
        for (int k = 0; k < 64; k++) {
            float4 w = *(const float4*)(sW1 + k * 128 + f0);
            float4 s0 = *(const float4*)(sS + k * 68 + t0);
            float4 s1 = *(const float4*)(sS + k * 68 + t0 + 4);
            float wa[4] = {w.x, w.y, w.z, w.w};
            float sa[8] = {s0.x, s0.y, s0.z, s0.w, s1.x, s1.y, s1.z, s1.w};
            #pragma unroll
            for (int fi = 0; fi < 4; fi++)
                #pragma unroll
                for (int tj = 0; tj < 8; tj++)
                    acc[fi][tj] = fmaf(wa[fi], sa[tj], acc[fi][tj]);
        }
        #pragma unroll
        for (int fi = 0; fi < 4; fi++) {
            float4 h0 = make_float4(fmaxf(acc[fi][0], 0.f), fmaxf(acc[fi][1], 0.f),
                                    fmaxf(acc[fi][2], 0.f), fmaxf(acc[fi][3], 0.f));
            float4 h1 = make_float4(fmaxf(acc[fi][4], 0.f), fmaxf(acc[fi][5], 0.f),
                                    fmaxf(acc[fi][6], 0.f), fmaxf(acc[fi][7], 0.f));
            *(float4*)(sH + (f0 + fi) * 68 + t0) = h0;
            *(float4*)(sH + (f0 + fi) * 68 + t0 + 4) = h1;
        }
    }
    __syncthreads();

    // Phase B: out[30][64] = W2 * H + b2
    {
        int t0 = (tid & 15) * 4;
        int o = (tid >> 4) * 2;
        float bb0 = (o < OO) ? b2[o] : 0.f;
        float bb1 = (o + 1 < OO) ? b2[o + 1] : 0.f;
        float a0[4] = {bb0, bb0, bb0, bb0};
        float a1[4] = {bb1, bb1, bb1, bb1};
        #pragma unroll 8
        for (int k = 0; k < 128; k++) {
            float4 h = *(const float4*)(sH + k * 68 + t0);
            float ha[4] = {h.x, h.y, h.z, h.w};
            float wo0 = sW2[k * 32 + o];
            float wo1 = sW2[k * 32 + o + 1];
            #pragma unroll
            for (int tj = 0; tj < 4; tj++) {
                a0[tj] = fmaf(wo0, ha[tj], a0[tj]);
                a1[tj] = fmaf(wo1, ha[tj], a1[tj]);
            }
        }
        if (o < OO)
            *(float4*)(out + ((size_t)b * OO + o) * LL + tt0 + t0) =
                make_float4(a0[0], a0[1], a0[2], a0[3]);
        if (o + 1 < OO)
            *(float4*)(out + ((size_t)b * OO + o + 1) * LL + tt0 + t0) =
                make_float4(a1[0], a1[1], a1[2], a1[3]);
    }
}

// ---------------- launch ----------------------------------------------------
extern "C" void kernel_launch(void* const* d_in, const int* in_sizes, int n_in,
                              void* d_out, int out_size)
{
    const int*   in_tok = (const int*)d_in[0];
    const int*   g_tok  = (const int*)d_in[1];
    const float* emb    = (const float*)d_in[2];
    const float* wc     = (const float*)d_in[3];
    const float* bc     = (const float*)d_in[4];
    const float* wf     = (const float*)d_in[5];
    const float* bf     = (const float*)d_in[6];
    const float* wg     = (const float*)d_in[7];
    const float* bg     = (const float*)d_in[8];
    const float* wlf    = (const float*)d_in[9];
    const float* blf    = (const float*)d_in[10];
    const float* wlg    = (const float*)d_in[11];
    const float* blg    = (const float*)d_in[12];
    const float* wres   = (const float*)d_in[13];
    const float* bres   = (const float*)d_in[14];
    const float* w1     = (const float*)d_in[15];
    const float* b1     = (const float*)d_in[16];
    const float* w2     = (const float*)d_in[17];
    const float* b2     = (const float*)d_in[18];
    float* out = (float*)d_out;

    const int LAYER_SMEM = (5 * 4096 + 3 * 64 * 68) * 4;   // 134144 B
    const int FINAL_SMEM = (64 * 68 + 64 * 128 + 128 * 68 + 128 * 32) * 4;  // 101376 B
    cudaFuncSetAttribute(k_layer, cudaFuncAttributeMaxDynamicSharedMemorySize, LAYER_SMEM);
    cudaFuncSetAttribute(k_final, cudaFuncAttributeMaxDynamicSharedMemorySize, FINAL_SMEM);

    k_precompute_M<<<VV, 64>>>(emb, wc);
    k_embg<<<BB, 256>>>(g_tok, emb);
    k_H<<<dim3(NDND, BB), 128>>>(wlf, blf, wlg, blg);
    k_init<<<dim3(LL / 64, BB), 256>>>(in_tok, bc);
    for (int i = 0; i < NDND; i++) {
        int d = 2 << i;  // 2^(i+1)
        k_layer<<<dim3(LL / 64, BB), 256, LAYER_SMEM>>>(wf, bf, wg, bg, wres, bres, i, d);
    }
    k_final<<<dim3(LL / 64, BB), 256, FINAL_SMEM>>>(w1, b1, w2, b2, out);
}